// round 1
// baseline (speedup 1.0000x reference)
#include <cuda_runtime.h>
#include <math.h>

// Problem constants
#define BB   8
#define CC   256
#define HW   4096
#define HW4  1024
#define EPSV 1e-5f

// ---------------- scratch (static __device__ — allocation-free) ----------------
__device__ float g_f_full[BB * 32 * HW];       //  4 MB  conv1 pre-pool
__device__ float g_g     [BB * 32 * HW];       //  4 MB  conv2 (g)
__device__ float g_h_full[BB * 128 * HW];      // 16 MB  conv3 pre-pool
__device__ float g_f     [BB * 32 * HW4];      //  1 MB  pooled f   [b][k][n]
__device__ float g_hh    [BB * 128 * HW4];     //  4 MB  pooled hh  [b][c][n]
__device__ float g_s     [(size_t)BB * HW4 * HW]; // 128 MB  s[b][n][m]
__device__ float g_cmax  [BB * HW];            // column max over n
__device__ float g_crl   [BB * HW];            // 1 / sum(exp)
__device__ float g_o     [BB * 128 * HW];      // 16 MB  o[b][c][m]

// ---------------------------------------------------------------------------
// Kernel 1: fused conv1/conv2/conv3 (1x1 conv + BN + ReLU), tiled SGEMM.
// grid (16 pixtiles, 6 sel, 8 batch), 256 threads.
//   sel 0 -> conv1 (OC 32) -> g_f_full
//   sel 1 -> conv2 (OC 32) -> g_g
//   sel 2..5 -> conv3 oc-chunk (OC 128) -> g_h_full
// Tile: 32 oc x 256 pix, K=256 in chunks of 32. Micro: 4 oc x 8 pix / thread.
// ---------------------------------------------------------------------------
__global__ __launch_bounds__(256) void conv123_kernel(
    const float* __restrict__ x,
    const float* __restrict__ w1, const float* __restrict__ b1, const float* __restrict__ s1,
    const float* __restrict__ t1, const float* __restrict__ m1, const float* __restrict__ v1,
    const float* __restrict__ w2, const float* __restrict__ b2, const float* __restrict__ s2,
    const float* __restrict__ t2, const float* __restrict__ m2, const float* __restrict__ v2,
    const float* __restrict__ w3, const float* __restrict__ b3, const float* __restrict__ s3,
    const float* __restrict__ t3, const float* __restrict__ m3, const float* __restrict__ v3)
{
    __shared__ float w_s[32][32];    // [k][oc]
    __shared__ float x_s[32][256];   // [k][pix]

    int sel = blockIdx.y;
    const float *w, *pb, *ps, *pt, *pm, *pv;
    float* out;
    int oc0, OC;
    if (sel == 0)      { w = w1; pb = b1; ps = s1; pt = t1; pm = m1; pv = v1; out = g_f_full; oc0 = 0; OC = 32; }
    else if (sel == 1) { w = w2; pb = b2; ps = s2; pt = t2; pm = m2; pv = v2; out = g_g;      oc0 = 0; OC = 32; }
    else               { w = w3; pb = b3; ps = s3; pt = t3; pm = m3; pv = v3; out = g_h_full; oc0 = (sel - 2) * 32; OC = 128; }

    int b  = blockIdx.z;
    int p0 = blockIdx.x * 256;
    int tid = threadIdx.x, ty = tid >> 5, tx = tid & 31;

    const float* xb = x + (size_t)b * CC * HW + p0;

    float acc[4][8];
#pragma unroll
    for (int u = 0; u < 4; u++)
#pragma unroll
        for (int v = 0; v < 8; v++) acc[u][v] = 0.f;

    for (int kc = 0; kc < CC; kc += 32) {
        // weights: w_s[k][oc] = w[(oc0+oc)*256 + kc+k]
#pragma unroll
        for (int e = tid; e < 32 * 32; e += 256) {
            int k = e >> 5, oc = e & 31;
            w_s[k][oc] = w[(size_t)(oc0 + oc) * CC + kc + k];
        }
        // x chunk, float4 coalesced
#pragma unroll
        for (int e = tid; e < 32 * 64; e += 256) {
            int k = e >> 6, p4 = e & 63;
            float4 val = *(const float4*)(xb + (size_t)(kc + k) * HW + p4 * 4);
            *(float4*)&x_s[k][p4 * 4] = val;
        }
        __syncthreads();
#pragma unroll
        for (int k = 0; k < 32; k++) {
            float wr[4], xr[8];
#pragma unroll
            for (int u = 0; u < 4; u++) wr[u] = w_s[k][ty * 4 + u];   // broadcast
#pragma unroll
            for (int v = 0; v < 8; v++) xr[v] = x_s[k][tx + 32 * v];  // conflict-free
#pragma unroll
            for (int u = 0; u < 4; u++)
#pragma unroll
                for (int v = 0; v < 8; v++) acc[u][v] = fmaf(wr[u], xr[v], acc[u][v]);
        }
        __syncthreads();
    }

#pragma unroll
    for (int u = 0; u < 4; u++) {
        int oc = oc0 + ty * 4 + u;
        float sc = ps[oc] * rsqrtf(pv[oc] + EPSV);
        float sh = (pb[oc] - pm[oc]) * sc + pt[oc];
        float* op = out + ((size_t)b * OC + oc) * HW + p0;
#pragma unroll
        for (int v = 0; v < 8; v++) {
            float y = acc[u][v] * sc + sh;
            op[tx + 32 * v] = fmaxf(y, 0.f);
        }
    }
}

// ---------------------------------------------------------------------------
// Kernel 2: 2x2 max pool. which=0: f_full->f, which=1: h_full->hh
// ---------------------------------------------------------------------------
__global__ void pool_kernel(int which)
{
    const float* in = which ? g_h_full : g_f_full;
    float* out      = which ? g_hh     : g_f;
    int total       = which ? BB * 128 * HW4 : BB * 32 * HW4;
    int i = blockIdx.x * 256 + threadIdx.x;
    if (i >= total) return;
    int j = i & 31, ii = (i >> 5) & 31, bc = i >> 10;
    const float* p = in + (size_t)bc * HW + (size_t)ii * 2 * 64 + 2 * j;
    out[i] = fmaxf(fmaxf(p[0], p[1]), fmaxf(p[64], p[65]));
}

// ---------------------------------------------------------------------------
// Kernel 3: s[b][n][m] = sum_k f[b][k][n] * g[b][k][m]   (K=32)
// grid (32 mtiles, 16 ntiles, 8 b), 256 threads. Tile 64n x 128m, micro 8x4.
// ---------------------------------------------------------------------------
__global__ __launch_bounds__(256) void sgemm_s_kernel()
{
    __shared__ float f_s[32][64];
    __shared__ float g_s2[32][128];
    int b = blockIdx.z, n0 = blockIdx.y * 64, m0 = blockIdx.x * 128;
    int tid = threadIdx.x, ty = tid >> 5, tx = tid & 31;

    const float* fb = g_f + (size_t)b * 32 * HW4 + n0;
    const float* gb = g_g + (size_t)b * 32 * HW  + m0;
#pragma unroll
    for (int e = tid; e < 2048; e += 256) { int k = e >> 6, n = e & 63;  f_s [k][n] = fb[(size_t)k * HW4 + n]; }
#pragma unroll
    for (int e = tid; e < 4096; e += 256) { int k = e >> 7, m = e & 127; g_s2[k][m] = gb[(size_t)k * HW  + m]; }
    __syncthreads();

    float acc[8][4];
#pragma unroll
    for (int u = 0; u < 8; u++)
#pragma unroll
        for (int v = 0; v < 4; v++) acc[u][v] = 0.f;

#pragma unroll
    for (int k = 0; k < 32; k++) {
        float fr[8], gr[4];
#pragma unroll
        for (int u = 0; u < 8; u++) fr[u] = f_s[k][ty + 8 * u];    // broadcast
#pragma unroll
        for (int v = 0; v < 4; v++) gr[v] = g_s2[k][tx + 32 * v];  // conflict-free
#pragma unroll
        for (int u = 0; u < 8; u++)
#pragma unroll
            for (int v = 0; v < 4; v++) acc[u][v] = fmaf(fr[u], gr[v], acc[u][v]);
    }

    float* sp = g_s + (size_t)b * HW4 * HW + (size_t)n0 * HW + m0;
#pragma unroll
    for (int u = 0; u < 8; u++)
#pragma unroll
        for (int v = 0; v < 4; v++)
            sp[(size_t)(ty + 8 * u) * HW + tx + 32 * v] = acc[u][v];
}

// ---------------------------------------------------------------------------
// Kernel 4: per-column (over n=1024) max and 1/sum(exp).
// One thread per (b, m) column; 256 CTAs x 128 threads.
// ---------------------------------------------------------------------------
__global__ __launch_bounds__(128) void softstats_kernel()
{
    int i = blockIdx.x * 128 + threadIdx.x;   // 0 .. 32767
    int b = i >> 12, m = i & 4095;
    const float* sp = g_s + (size_t)b * HW4 * HW + m;
    float mx = -1e30f;
#pragma unroll 16
    for (int n = 0; n < HW4; n++) mx = fmaxf(mx, sp[(size_t)n * HW]);
    float l = 0.f;
#pragma unroll 8
    for (int n = 0; n < HW4; n++) l += __expf(sp[(size_t)n * HW] - mx);
    g_cmax[i] = mx;
    g_crl[i]  = 1.f / l;
}

// ---------------------------------------------------------------------------
// Kernel 5: o[b][c][m] = (1/l[m]) * sum_n hh[b][c][n] * exp(s[b][n][m]-max[m])
// grid (32 mtiles, 8 b), 256 threads. Tile 128c x 128m, K=1024 in chunks of 32.
// Micro-tile 16c x 4m per thread. exp applied while staging s into smem.
// ---------------------------------------------------------------------------
__global__ __launch_bounds__(256) void attn_o_kernel()
{
    __shared__ float a_s[32][133];   // [n][c], pad 133 -> conflict-free stores
    __shared__ float b_s[32][128];   // [n][m]  (holds exp(s - max))
    __shared__ float mx_s[128];

    int b = blockIdx.y, m0 = blockIdx.x * 128;
    int tid = threadIdx.x, ty = tid >> 5, tx = tid & 31;

    if (tid < 128) mx_s[tid] = g_cmax[b * HW + m0 + tid];

    const float* hb = g_hh + (size_t)b * 128 * HW4;
    const float* sb = g_s  + (size_t)b * HW4 * HW + m0;

    float acc[16][4];
#pragma unroll
    for (int u = 0; u < 16; u++)
#pragma unroll
        for (int v = 0; v < 4; v++) acc[u][v] = 0.f;

    __syncthreads();

    for (int n0 = 0; n0 < HW4; n0 += 32) {
#pragma unroll
        for (int j = 0; j < 16; j++) {
            int e = tid + 256 * j; int n = e & 31, c = e >> 5;
            a_s[n][c] = hb[(size_t)c * HW4 + n0 + n];
        }
#pragma unroll
        for (int j = 0; j < 16; j++) {
            int e = tid + 256 * j; int n = e >> 7, m = e & 127;
            b_s[n][m] = __expf(sb[(size_t)(n0 + n) * HW + m] - mx_s[m]);
        }
        __syncthreads();
#pragma unroll
        for (int k = 0; k < 32; k++) {
            float ar[16], br[4];
#pragma unroll
            for (int u = 0; u < 16; u++) ar[u] = a_s[k][ty + 8 * u];   // broadcast
#pragma unroll
            for (int v = 0; v < 4; v++) br[v] = b_s[k][tx + 32 * v];   // conflict-free
#pragma unroll
            for (int u = 0; u < 16; u++)
#pragma unroll
                for (int v = 0; v < 4; v++) acc[u][v] = fmaf(ar[u], br[v], acc[u][v]);
        }
        __syncthreads();
    }

    float* op = g_o + (size_t)b * 128 * HW + m0;
#pragma unroll
    for (int u = 0; u < 16; u++) {
        int c = ty + 8 * u;
#pragma unroll
        for (int v = 0; v < 4; v++) {
            int m = tx + 32 * v;
            op[(size_t)c * HW + m] = acc[u][v] * g_crl[b * HW + m0 + m];
        }
    }
}

// ---------------------------------------------------------------------------
// Kernel 6: out = gamma * BN(conv4(o)) + x
// grid (32 ptiles, 4 octiles, 8 b), 256 threads. Tile 64oc x 128p, K=128.
// Micro 8oc x 4p per thread.
// ---------------------------------------------------------------------------
__global__ __launch_bounds__(256) void conv4_res_kernel(
    const float* __restrict__ x,
    const float* __restrict__ w4, const float* __restrict__ b4, const float* __restrict__ s4,
    const float* __restrict__ t4, const float* __restrict__ m4, const float* __restrict__ v4,
    const float* __restrict__ gamma, float* __restrict__ out)
{
    __shared__ float w_s[32][64];    // [k][oc]
    __shared__ float o_s[32][128];   // [k][p]
    int b = blockIdx.z, oc0 = blockIdx.y * 64, p0 = blockIdx.x * 128;
    int tid = threadIdx.x, ty = tid >> 5, tx = tid & 31;

    const float* ob = g_o + (size_t)b * 128 * HW + p0;

    float acc[8][4];
#pragma unroll
    for (int u = 0; u < 8; u++)
#pragma unroll
        for (int v = 0; v < 4; v++) acc[u][v] = 0.f;

    for (int kc = 0; kc < 128; kc += 32) {
#pragma unroll
        for (int e = tid; e < 2048; e += 256) { int k = e >> 6, oc = e & 63; w_s[k][oc] = w4[(size_t)(oc0 + oc) * 128 + kc + k]; }
#pragma unroll
        for (int e = tid; e < 4096; e += 256) { int k = e >> 7, p = e & 127; o_s[k][p] = ob[(size_t)(kc + k) * HW + p]; }
        __syncthreads();
#pragma unroll
        for (int k = 0; k < 32; k++) {
            float wr[8], pr[4];
#pragma unroll
            for (int u = 0; u < 8; u++) wr[u] = w_s[k][ty + 8 * u];    // broadcast
#pragma unroll
            for (int v = 0; v < 4; v++) pr[v] = o_s[k][tx + 32 * v];   // conflict-free
#pragma unroll
            for (int u = 0; u < 8; u++)
#pragma unroll
                for (int v = 0; v < 4; v++) acc[u][v] = fmaf(wr[u], pr[v], acc[u][v]);
        }
        __syncthreads();
    }

    float gm = *gamma;
#pragma unroll
    for (int u = 0; u < 8; u++) {
        int oc = oc0 + ty + 8 * u;
        float sc = s4[oc] * rsqrtf(v4[oc] + EPSV);
        float sh = (b4[oc] - m4[oc]) * sc + t4[oc];
        const float* xp = x   + ((size_t)b * CC + oc) * HW + p0;
        float*       op = out + ((size_t)b * CC + oc) * HW + p0;
#pragma unroll
        for (int v = 0; v < 4; v++) {
            int p = tx + 32 * v;
            op[p] = gm * (acc[u][v] * sc + sh) + xp[p];
        }
    }
}

// ---------------------------------------------------------------------------
extern "C" void kernel_launch(void* const* d_in, const int* in_sizes, int n_in,
                              void* d_out, int out_size)
{
    (void)in_sizes; (void)n_in; (void)out_size;
    const float* x = (const float*)d_in[0];
#define P(i) ((const float*)d_in[i])

    conv123_kernel<<<dim3(16, 6, 8), 256>>>(
        x,
        P(1), P(2), P(3), P(4), P(5), P(6),       // conv1
        P(7), P(8), P(9), P(10), P(11), P(12),    // conv2
        P(13), P(14), P(15), P(16), P(17), P(18));// conv3

    pool_kernel<<<(BB * 32  * HW4 + 255) / 256, 256>>>(0);
    pool_kernel<<<(BB * 128 * HW4 + 255) / 256, 256>>>(1);

    sgemm_s_kernel<<<dim3(32, 16, 8), 256>>>();
    softstats_kernel<<<256, 128>>>();
    attn_o_kernel<<<dim3(32, 8), 256>>>();

    conv4_res_kernel<<<dim3(32, 4, 8), 256>>>(
        x, P(19), P(20), P(21), P(22), P(23), P(24), P(25), (float*)d_out);
#undef P
}

// round 2
// speedup vs baseline: 1.2719x; 1.2719x over previous
#include <cuda_runtime.h>
#include <math.h>

// Problem constants
#define BB   8
#define CC   256
#define HW   4096
#define HW4  1024
#define EPSV 1e-5f

// ---------------- scratch (static __device__ — allocation-free) ----------------
__device__ float g_g [BB * 32 * HW];    //  4 MB  conv2 (g), full res [b][k][m]
__device__ float g_f [BB * 32 * HW4];   //  1 MB  pooled f   [b][k][n]
__device__ float g_hh[BB * 128 * HW4];  //  4 MB  pooled hh  [b][c][n]
__device__ float g_o [BB * 128 * HW];   // 16 MB  o          [b][c][m]

// ---------------------------------------------------------------------------
// Kernel 1: fused conv1/conv2/conv3 (1x1 conv + BN + ReLU) with fused 2x2
// max-pool for conv1/conv3. grid (16 pixtiles, 6 sel, 8 batch), 256 threads.
//   sel 0 -> conv1 (OC 32)  -> pooled  -> g_f
//   sel 1 -> conv2 (OC 32)  -> fullres -> g_g
//   sel 2..5 -> conv3 chunk -> pooled  -> g_hh
// Tile: 32 oc x 256 pix (4 rows of W=64), K=256 in chunks of 32.
// ---------------------------------------------------------------------------
__global__ __launch_bounds__(256) void conv123_kernel(
    const float* __restrict__ x,
    const float* __restrict__ w1, const float* __restrict__ b1, const float* __restrict__ s1,
    const float* __restrict__ t1, const float* __restrict__ m1, const float* __restrict__ v1,
    const float* __restrict__ w2, const float* __restrict__ b2, const float* __restrict__ s2,
    const float* __restrict__ t2, const float* __restrict__ m2, const float* __restrict__ v2,
    const float* __restrict__ w3, const float* __restrict__ b3, const float* __restrict__ s3,
    const float* __restrict__ t3, const float* __restrict__ m3, const float* __restrict__ v3)
{
    __shared__ float w_s[32][32];    // [k][oc]
    __shared__ float x_s[32][256];   // [k][pix], reused as y staging for pooling

    int sel = blockIdx.y;
    const float *w, *pb, *ps, *pt, *pm, *pv;
    int oc0;
    if (sel == 0)      { w = w1; pb = b1; ps = s1; pt = t1; pm = m1; pv = v1; oc0 = 0; }
    else if (sel == 1) { w = w2; pb = b2; ps = s2; pt = t2; pm = m2; pv = v2; oc0 = 0; }
    else               { w = w3; pb = b3; ps = s3; pt = t3; pm = m3; pv = v3; oc0 = (sel - 2) * 32; }

    int b  = blockIdx.z;
    int p0 = blockIdx.x * 256;
    int tid = threadIdx.x, ty = tid >> 5, tx = tid & 31;

    const float* xb = x + (size_t)b * CC * HW + p0;

    float acc[4][8];
#pragma unroll
    for (int u = 0; u < 4; u++)
#pragma unroll
        for (int v = 0; v < 8; v++) acc[u][v] = 0.f;

    for (int kc = 0; kc < CC; kc += 32) {
#pragma unroll
        for (int e = tid; e < 32 * 32; e += 256) {
            int k = e >> 5, oc = e & 31;
            w_s[k][oc] = w[(size_t)(oc0 + oc) * CC + kc + k];
        }
#pragma unroll
        for (int e = tid; e < 32 * 64; e += 256) {
            int k = e >> 6, p4 = e & 63;
            float4 val = *(const float4*)(xb + (size_t)(kc + k) * HW + p4 * 4);
            *(float4*)&x_s[k][p4 * 4] = val;
        }
        __syncthreads();
#pragma unroll
        for (int k = 0; k < 32; k++) {
            float wr[4], xr[8];
#pragma unroll
            for (int u = 0; u < 4; u++) wr[u] = w_s[k][ty * 4 + u];
#pragma unroll
            for (int v = 0; v < 8; v++) xr[v] = x_s[k][tx + 32 * v];
#pragma unroll
            for (int u = 0; u < 4; u++)
#pragma unroll
                for (int v = 0; v < 8; v++) acc[u][v] = fmaf(wr[u], xr[v], acc[u][v]);
        }
        __syncthreads();
    }

    if (sel == 1) {
        // conv2 (g): write full resolution directly
#pragma unroll
        for (int u = 0; u < 4; u++) {
            int oc = ty * 4 + u;
            float sc = ps[oc] * rsqrtf(pv[oc] + EPSV);
            float sh = (pb[oc] - pm[oc]) * sc + pt[oc];
            float* op = g_g + ((size_t)b * 32 + oc) * HW + p0;
#pragma unroll
            for (int v = 0; v < 8; v++)
                op[tx + 32 * v] = fmaxf(acc[u][v] * sc + sh, 0.f);
        }
        return;
    }

    // conv1 / conv3: stage BN+ReLU tile in smem, then pooled write.
    float* y_s = &x_s[0][0];   // 32 oc x 256 pix
#pragma unroll
    for (int u = 0; u < 4; u++) {
        int ocl = ty * 4 + u;
        int oc  = oc0 + ocl;
        float sc = ps[oc] * rsqrtf(pv[oc] + EPSV);
        float sh = (pb[oc] - pm[oc]) * sc + pt[oc];
#pragma unroll
        for (int v = 0; v < 8; v++)
            y_s[ocl * 256 + tx + 32 * v] = fmaxf(acc[u][v] * sc + sh, 0.f);
    }
    __syncthreads();

    int PR0 = p0 >> 7;   // pooled base row (tile covers 4 full rows = 2 pooled rows)
    float* out = (sel == 0) ? (g_f + (size_t)b * 32 * HW4)
                            : (g_hh + (size_t)b * 128 * HW4 + (size_t)oc0 * HW4);
#pragma unroll
    for (int j = 0; j < 8; j++) {
        int e = tid + 256 * j;         // 0 .. 2047
        int ocl = e >> 6, q = e & 63;
        int pq = q >> 5, col = q & 31;
        int base = ocl * 256 + pq * 128 + 2 * col;
        float v01 = fmaxf(y_s[base],      y_s[base + 1]);
        float v23 = fmaxf(y_s[base + 64], y_s[base + 65]);
        int n = (PR0 + pq) * 32 + col;
        out[(size_t)ocl * HW4 + n] = fmaxf(v01, v23);
    }
}

// ---------------------------------------------------------------------------
// Kernel 2: flash attention.
//   s[n][m] = sum_k f[k][n] g[k][m]   (K=32, n=1024, m=4096)
//   beta    = softmax over n
//   o[c][m] = sum_n hh[c][n] beta[n][m]
// grid (32 mtiles, 8 b), 256 threads as 16x16. m-tile 128, n-tile 32.
// Online softmax per column m; s never hits global memory.
// ---------------------------------------------------------------------------
struct FlashSmem {
    float g[32][128];    // g tile [k][m]      (fixed per CTA)
    float f[32][32];     // f tile [k][n]
    float p[32][129];    // exp(s) tile [n][m] (padded)
    float a[32][129];    // hh tile [n][c]     (padded, transposed store)
    float red[16][129];  // column reduction scratch (padded)
    float mx[128];       // running column max
    float l[128];        // running sum of exp
    float fac[128];      // rescale factor this tile
};

__global__ __launch_bounds__(256) void flash_kernel()
{
    extern __shared__ char smraw[];
    FlashSmem* S = (FlashSmem*)smraw;

    int b = blockIdx.y, m0 = blockIdx.x * 128;
    int tid = threadIdx.x;
    int tx16 = tid & 15, ty16 = tid >> 4;

    const float* gb = g_g  + (size_t)b * 32  * HW + m0;
    const float* fb = g_f  + (size_t)b * 32  * HW4;
    const float* hb = g_hh + (size_t)b * 128 * HW4;

    if (tid < 128) { S->mx[tid] = -INFINITY; S->l[tid] = 0.f; }

    // load g tile once (16 KB)
#pragma unroll
    for (int e = tid; e < 4096; e += 256) {
        int k = e >> 7, m = e & 127;
        S->g[k][m] = gb[(size_t)k * HW + m];
    }

    float acc[8][8];
#pragma unroll
    for (int u = 0; u < 8; u++)
#pragma unroll
        for (int v = 0; v < 8; v++) acc[u][v] = 0.f;

    for (int n0 = 0; n0 < HW4; n0 += 32) {
        // load f tile [32k][32n] and hh tile [32n][128c]
#pragma unroll
        for (int e = tid; e < 1024; e += 256) {
            int k = e >> 5, n = e & 31;
            S->f[k][n] = fb[(size_t)k * HW4 + n0 + n];
        }
#pragma unroll
        for (int e = tid; e < 4096; e += 256) {
            int n = e & 31, c = e >> 5;
            S->a[n][c] = hb[(size_t)c * HW4 + n0 + n];
        }
        __syncthreads();   // S1: tiles ready (also fences prev-iter PV)

        // ---- QK: s[n][m], per-thread n = ty16+16u (u<2), m = tx16+16v (v<8)
        float sreg[2][8];
#pragma unroll
        for (int u = 0; u < 2; u++)
#pragma unroll
            for (int v = 0; v < 8; v++) sreg[u][v] = 0.f;
#pragma unroll
        for (int k = 0; k < 32; k++) {
            float fr[2], gr[8];
#pragma unroll
            for (int u = 0; u < 2; u++) fr[u] = S->f[k][ty16 + 16 * u];
#pragma unroll
            for (int v = 0; v < 8; v++) gr[v] = S->g[k][tx16 + 16 * v];
#pragma unroll
            for (int u = 0; u < 2; u++)
#pragma unroll
                for (int v = 0; v < 8; v++) sreg[u][v] = fmaf(fr[u], gr[v], sreg[u][v]);
        }

        // ---- column max of the tile
#pragma unroll
        for (int v = 0; v < 8; v++)
            S->red[ty16][tx16 + 16 * v] = fmaxf(sreg[0][v], sreg[1][v]);
        __syncthreads();   // S2
        if (tid < 128) {
            int m = tid;
            float t = S->red[0][m];
#pragma unroll
            for (int j = 1; j < 16; j++) t = fmaxf(t, S->red[j][m]);
            float nm = fmaxf(S->mx[m], t);
            S->fac[m] = __expf(S->mx[m] - nm);
            S->mx[m]  = nm;
        }
        __syncthreads();   // S3: mx/fac ready

        // ---- exp, store p, partial column sums
#pragma unroll
        for (int v = 0; v < 8; v++) {
            int m = tx16 + 16 * v;
            float mxm = S->mx[m];
            float e0 = __expf(sreg[0][v] - mxm);
            float e1 = __expf(sreg[1][v] - mxm);
            S->p[ty16][m]      = e0;
            S->p[ty16 + 16][m] = e1;
            S->red[ty16][m] = e0 + e1;
        }
        __syncthreads();   // S4: p + partial sums ready

        if (tid < 128) {
            int m = tid;
            float t = 0.f;
#pragma unroll
            for (int j = 0; j < 16; j++) t += S->red[j][m];
            S->l[m] = S->l[m] * S->fac[m] + t;
        }

        // ---- rescale accumulator, then PV accumulate
        float fv[8];
#pragma unroll
        for (int v = 0; v < 8; v++) fv[v] = S->fac[tx16 + 16 * v];
#pragma unroll
        for (int u = 0; u < 8; u++)
#pragma unroll
            for (int v = 0; v < 8; v++) acc[u][v] *= fv[v];

#pragma unroll
        for (int k = 0; k < 32; k++) {
            float ar[8], br[8];
#pragma unroll
            for (int u = 0; u < 8; u++) ar[u] = S->a[k][ty16 + 16 * u];
#pragma unroll
            for (int v = 0; v < 8; v++) br[v] = S->p[k][tx16 + 16 * v];
#pragma unroll
            for (int u = 0; u < 8; u++)
#pragma unroll
                for (int v = 0; v < 8; v++) acc[u][v] = fmaf(ar[u], br[v], acc[u][v]);
        }
        __syncthreads();   // S0: done with f/a/p/red this tile
    }

    // ---- epilogue: o = acc / l
    float rl[8];
#pragma unroll
    for (int v = 0; v < 8; v++) rl[v] = 1.f / S->l[tx16 + 16 * v];
    float* ob = g_o + (size_t)b * 128 * HW + m0;
#pragma unroll
    for (int u = 0; u < 8; u++) {
        int c = ty16 + 16 * u;
#pragma unroll
        for (int v = 0; v < 8; v++)
            ob[(size_t)c * HW + tx16 + 16 * v] = acc[u][v] * rl[v];
    }
}

// ---------------------------------------------------------------------------
// Kernel 3: out = gamma * BN(conv4(o)) + x
// grid (32 ptiles, 4 octiles, 8 b), 256 threads. Tile 64oc x 128p, K=128.
// ---------------------------------------------------------------------------
__global__ __launch_bounds__(256) void conv4_res_kernel(
    const float* __restrict__ x,
    const float* __restrict__ w4, const float* __restrict__ b4, const float* __restrict__ s4,
    const float* __restrict__ t4, const float* __restrict__ m4, const float* __restrict__ v4,
    const float* __restrict__ gamma, float* __restrict__ out)
{
    __shared__ float w_s[32][64];
    __shared__ float o_s[32][128];
    int b = blockIdx.z, oc0 = blockIdx.y * 64, p0 = blockIdx.x * 128;
    int tid = threadIdx.x, ty = tid >> 5, tx = tid & 31;

    const float* ob = g_o + (size_t)b * 128 * HW + p0;

    float acc[8][4];
#pragma unroll
    for (int u = 0; u < 8; u++)
#pragma unroll
        for (int v = 0; v < 4; v++) acc[u][v] = 0.f;

    for (int kc = 0; kc < 128; kc += 32) {
#pragma unroll
        for (int e = tid; e < 2048; e += 256) { int k = e >> 6, oc = e & 63; w_s[k][oc] = w4[(size_t)(oc0 + oc) * 128 + kc + k]; }
#pragma unroll
        for (int e = tid; e < 4096; e += 256) { int k = e >> 7, p = e & 127; o_s[k][p] = ob[(size_t)(kc + k) * HW + p]; }
        __syncthreads();
#pragma unroll
        for (int k = 0; k < 32; k++) {
            float wr[8], pr[4];
#pragma unroll
            for (int u = 0; u < 8; u++) wr[u] = w_s[k][ty + 8 * u];
#pragma unroll
            for (int v = 0; v < 4; v++) pr[v] = o_s[k][tx + 32 * v];
#pragma unroll
            for (int u = 0; u < 8; u++)
#pragma unroll
                for (int v = 0; v < 4; v++) acc[u][v] = fmaf(wr[u], pr[v], acc[u][v]);
        }
        __syncthreads();
    }

    float gm = *gamma;
#pragma unroll
    for (int u = 0; u < 8; u++) {
        int oc = oc0 + ty + 8 * u;
        float sc = s4[oc] * rsqrtf(v4[oc] + EPSV);
        float sh = (b4[oc] - m4[oc]) * sc + t4[oc];
        const float* xp = x   + ((size_t)b * CC + oc) * HW + p0;
        float*       op = out + ((size_t)b * CC + oc) * HW + p0;
#pragma unroll
        for (int v = 0; v < 4; v++) {
            int p = tx + 32 * v;
            op[p] = gm * (acc[u][v] * sc + sh) + xp[p];
        }
    }
}

// ---------------------------------------------------------------------------
extern "C" void kernel_launch(void* const* d_in, const int* in_sizes, int n_in,
                              void* d_out, int out_size)
{
    (void)in_sizes; (void)n_in; (void)out_size;
    const float* x = (const float*)d_in[0];
#define P(i) ((const float*)d_in[i])

    conv123_kernel<<<dim3(16, 6, 8), 256>>>(
        x,
        P(1), P(2), P(3), P(4), P(5), P(6),        // conv1
        P(7), P(8), P(9), P(10), P(11), P(12),     // conv2
        P(13), P(14), P(15), P(16), P(17), P(18)); // conv3

    cudaFuncSetAttribute(flash_kernel, cudaFuncAttributeMaxDynamicSharedMemorySize,
                         (int)sizeof(FlashSmem));
    flash_kernel<<<dim3(32, 8), 256, sizeof(FlashSmem)>>>();

    conv4_res_kernel<<<dim3(32, 4, 8), 256>>>(
        x, P(19), P(20), P(21), P(22), P(23), P(24), P(25), (float*)d_out);
#undef P
}

// round 3
// speedup vs baseline: 1.3398x; 1.0534x over previous
#include <cuda_runtime.h>
#include <math.h>

// Problem constants
#define BB   8
#define CC   256
#define HW   4096
#define HW4  1024
#define EPSV 1e-5f

typedef unsigned long long u64;

// ---- packed f32x2 helpers (sm_103a) ----
__device__ __forceinline__ u64 pk2(float lo, float hi) {
    u64 r; asm("mov.b64 %0, {%1, %2};" : "=l"(r) : "f"(lo), "f"(hi)); return r;
}
__device__ __forceinline__ u64 dup2(float x) {
    u64 r; asm("mov.b64 %0, {%1, %1};" : "=l"(r) : "f"(x)); return r;
}
__device__ __forceinline__ void upk2(float& lo, float& hi, u64 v) {
    asm("mov.b64 {%0, %1}, %2;" : "=f"(lo), "=f"(hi) : "l"(v));
}
__device__ __forceinline__ u64 ffma2(u64 a, u64 b, u64 c) {
    u64 d; asm("fma.rn.f32x2 %0, %1, %2, %3;" : "=l"(d) : "l"(a), "l"(b), "l"(c)); return d;
}
__device__ __forceinline__ u64 fmul2(u64 a, u64 b) {
    u64 d; asm("mul.rn.f32x2 %0, %1, %2;" : "=l"(d) : "l"(a), "l"(b)); return d;
}

// ---------------- scratch (static __device__ — allocation-free) ----------------
__device__ float g_g [BB * 32 * HW];    //  4 MB  conv2 (g), full res [b][k][m]
__device__ float g_f [BB * 32 * HW4];   //  1 MB  pooled f   [b][k][n]
__device__ float g_hh[BB * 128 * HW4];  //  4 MB  pooled hh  [b][c][n]
__device__ float g_o [BB * 128 * HW];   // 16 MB  o          [b][c][m]

// ---------------------------------------------------------------------------
// Kernel 1: fused conv1/conv2/conv3 (1x1 conv + BN + ReLU), 2x2 maxpool done
// in registers for conv1/conv3. grid (16 pixtiles, 6 sel, 8 batch), 256 thr.
// Tile: 32 oc x 256 pix (4 image rows of 64). Micro: 4 oc x 4 pixel-PAIRS.
// Pixel pair (2*tx, 2*tx+1) in image row v -> packed f32x2 lane.
// ---------------------------------------------------------------------------
__global__ __launch_bounds__(256) void conv123_kernel(
    const float* __restrict__ x,
    const float* __restrict__ w1, const float* __restrict__ b1, const float* __restrict__ s1,
    const float* __restrict__ t1, const float* __restrict__ m1, const float* __restrict__ v1,
    const float* __restrict__ w2, const float* __restrict__ b2, const float* __restrict__ s2,
    const float* __restrict__ t2, const float* __restrict__ m2, const float* __restrict__ v2,
    const float* __restrict__ w3, const float* __restrict__ b3, const float* __restrict__ s3,
    const float* __restrict__ t3, const float* __restrict__ m3, const float* __restrict__ v3)
{
    __shared__ float w_s[32][32];    // [k][oc]
    __shared__ float x_s[32][256];   // [k][pix]

    int sel = blockIdx.y;
    const float *w, *pb, *ps, *pt, *pm, *pv;
    int oc0;
    if (sel == 0)      { w = w1; pb = b1; ps = s1; pt = t1; pm = m1; pv = v1; oc0 = 0; }
    else if (sel == 1) { w = w2; pb = b2; ps = s2; pt = t2; pm = m2; pv = v2; oc0 = 0; }
    else               { w = w3; pb = b3; ps = s3; pt = t3; pm = m3; pv = v3; oc0 = (sel - 2) * 32; }

    int b  = blockIdx.z;
    int p0 = blockIdx.x * 256;
    int tid = threadIdx.x, ty = tid >> 5, tx = tid & 31;

    const float* xb = x + (size_t)b * CC * HW + p0;

    u64 acc[4][4];
#pragma unroll
    for (int u = 0; u < 4; u++)
#pragma unroll
        for (int v = 0; v < 4; v++) acc[u][v] = 0ull;

    for (int kc = 0; kc < CC; kc += 32) {
#pragma unroll
        for (int e = tid; e < 32 * 32; e += 256) {
            int k = e >> 5, oc = e & 31;
            w_s[k][oc] = w[(size_t)(oc0 + oc) * CC + kc + k];
        }
#pragma unroll
        for (int e = tid; e < 32 * 64; e += 256) {
            int k = e >> 6, p4 = e & 63;
            float4 val = *(const float4*)(xb + (size_t)(kc + k) * HW + p4 * 4);
            *(float4*)&x_s[k][p4 * 4] = val;
        }
        __syncthreads();
#pragma unroll
        for (int k = 0; k < 32; k++) {
            u64 wr[4], xr[4];
#pragma unroll
            for (int u = 0; u < 4; u++) wr[u] = dup2(w_s[k][ty * 4 + u]);  // broadcast
#pragma unroll
            for (int v = 0; v < 4; v++) xr[v] = *(const u64*)&x_s[k][2 * tx + 64 * v];
#pragma unroll
            for (int u = 0; u < 4; u++)
#pragma unroll
                for (int v = 0; v < 4; v++) acc[u][v] = ffma2(xr[v], wr[u], acc[u][v]);
        }
        __syncthreads();
    }

    if (sel == 1) {
        // conv2 (g): full-res packed stores
#pragma unroll
        for (int u = 0; u < 4; u++) {
            int oc = ty * 4 + u;
            float sc = ps[oc] * rsqrtf(pv[oc] + EPSV);
            float sh = (pb[oc] - pm[oc]) * sc + pt[oc];
            float* op = g_g + ((size_t)b * 32 + oc) * HW + p0;
#pragma unroll
            for (int v = 0; v < 4; v++) {
                float lo, hi; upk2(lo, hi, acc[u][v]);
                float2 y = make_float2(fmaxf(lo * sc + sh, 0.f), fmaxf(hi * sc + sh, 0.f));
                *(float2*)&op[2 * tx + 64 * v] = y;
            }
        }
        return;
    }

    // conv1 / conv3: in-register 2x2 maxpool.
    // pair = horizontal pool pair; v = image row within the 4-row tile.
    int PR0 = p0 >> 7;   // pooled base row (2 pooled rows per tile)
    float* out = (sel == 0) ? (g_f + (size_t)b * 32 * HW4)
                            : (g_hh + (size_t)b * 128 * HW4 + (size_t)oc0 * HW4);
#pragma unroll
    for (int u = 0; u < 4; u++) {
        int ocl = ty * 4 + u;
        int oc  = oc0 + ocl;
        float sc = ps[oc] * rsqrtf(pv[oc] + EPSV);
        float sh = (pb[oc] - pm[oc]) * sc + pt[oc];
        float hm[4];
#pragma unroll
        for (int v = 0; v < 4; v++) {
            float lo, hi; upk2(lo, hi, acc[u][v]);
            hm[v] = fmaxf(fmaxf(lo * sc + sh, 0.f), fmaxf(hi * sc + sh, 0.f));
        }
        out[(size_t)ocl * HW4 + (PR0 + 0) * 32 + tx] = fmaxf(hm[0], hm[1]);
        out[(size_t)ocl * HW4 + (PR0 + 1) * 32 + tx] = fmaxf(hm[2], hm[3]);
    }
}

// ---------------------------------------------------------------------------
// Kernel 2: flash attention, packed f32x2 along m.
//   s[n][m] = sum_k f[k][n] g[k][m]   (K=32, n=1024, m=4096)
//   beta    = softmax over n; o[c][m] = sum_n hh[c][n] beta[n][m]
// grid (32 mtiles, 8 b), 256 threads as 16x16. m-tile 128, n-tile 32.
// Per thread: 8 c-rows x 4 m-pairs (m = 2*tx16 + 32*v).
// ---------------------------------------------------------------------------
struct FlashSmem {
    float g[32][128];    // g tile [k][m]
    float f[32][32];     // f tile [k][n]
    float p[32][130];    // exp(s) tile [n][m] (even pad -> 8B-aligned rows)
    float a[32][129];    // hh tile [n][c]
    float red[16][130];  // column reduction scratch
    float mx[128];
    float l[128];
    float fac[128];
};

__global__ __launch_bounds__(256) void flash_kernel()
{
    extern __shared__ char smraw[];
    FlashSmem* S = (FlashSmem*)smraw;

    int b = blockIdx.y, m0 = blockIdx.x * 128;
    int tid = threadIdx.x;
    int tx16 = tid & 15, ty16 = tid >> 4;
    int mB = 2 * tx16;   // pair base within tile

    const float* gb = g_g  + (size_t)b * 32  * HW + m0;
    const float* fb = g_f  + (size_t)b * 32  * HW4;
    const float* hb = g_hh + (size_t)b * 128 * HW4;

    if (tid < 128) { S->mx[tid] = -INFINITY; S->l[tid] = 0.f; }

#pragma unroll
    for (int e = tid; e < 4096; e += 256) {
        int k = e >> 7, m = e & 127;
        S->g[k][m] = gb[(size_t)k * HW + m];
    }

    u64 acc[8][4];
#pragma unroll
    for (int u = 0; u < 8; u++)
#pragma unroll
        for (int v = 0; v < 4; v++) acc[u][v] = 0ull;

    for (int n0 = 0; n0 < HW4; n0 += 32) {
#pragma unroll
        for (int e = tid; e < 1024; e += 256) {
            int k = e >> 5, n = e & 31;
            S->f[k][n] = fb[(size_t)k * HW4 + n0 + n];
        }
#pragma unroll
        for (int e = tid; e < 4096; e += 256) {
            int n = e & 31, c = e >> 5;
            S->a[n][c] = hb[(size_t)c * HW4 + n0 + n];
        }
        __syncthreads();   // S1: tiles ready (fences prev-iter PV)

        // ---- QK: packed over m pairs. rows n = ty16, ty16+16
        u64 sreg[2][4];
#pragma unroll
        for (int u = 0; u < 2; u++)
#pragma unroll
            for (int v = 0; v < 4; v++) sreg[u][v] = 0ull;
#pragma unroll
        for (int k = 0; k < 32; k++) {
            u64 fr[2], gr[4];
            fr[0] = dup2(S->f[k][ty16]);
            fr[1] = dup2(S->f[k][ty16 + 16]);
#pragma unroll
            for (int v = 0; v < 4; v++) gr[v] = *(const u64*)&S->g[k][mB + 32 * v];
#pragma unroll
            for (int u = 0; u < 2; u++)
#pragma unroll
                for (int v = 0; v < 4; v++) sreg[u][v] = ffma2(gr[v], fr[u], sreg[u][v]);
        }

        // ---- per-tile column max partials
#pragma unroll
        for (int v = 0; v < 4; v++) {
            float l0, h0, l1, h1;
            upk2(l0, h0, sreg[0][v]); upk2(l1, h1, sreg[1][v]);
            *(float2*)&S->red[ty16][mB + 32 * v] =
                make_float2(fmaxf(l0, l1), fmaxf(h0, h1));
        }
        __syncthreads();   // S2
        if (tid < 128) {
            int m = tid;
            float t = S->red[0][m];
#pragma unroll
            for (int j = 1; j < 16; j++) t = fmaxf(t, S->red[j][m]);
            float nm = fmaxf(S->mx[m], t);
            S->fac[m] = __expf(S->mx[m] - nm);
            S->mx[m]  = nm;
        }
        __syncthreads();   // S3: mx/fac ready

        // ---- exp + p store + partial column sums
#pragma unroll
        for (int v = 0; v < 4; v++) {
            int m = mB + 32 * v;
            float mlo = S->mx[m], mhi = S->mx[m + 1];
            float l0, h0, l1, h1;
            upk2(l0, h0, sreg[0][v]); upk2(l1, h1, sreg[1][v]);
            float e0l = __expf(l0 - mlo), e0h = __expf(h0 - mhi);
            float e1l = __expf(l1 - mlo), e1h = __expf(h1 - mhi);
            *(float2*)&S->p[ty16][m]      = make_float2(e0l, e0h);
            *(float2*)&S->p[ty16 + 16][m] = make_float2(e1l, e1h);
            *(float2*)&S->red[ty16][m]    = make_float2(e0l + e1l, e0h + e1h);
        }
        __syncthreads();   // S4: p + partials ready

        if (tid < 128) {
            int m = tid;
            float t = 0.f;
#pragma unroll
            for (int j = 0; j < 16; j++) t += S->red[j][m];
            S->l[m] = S->l[m] * S->fac[m] + t;
        }

        // ---- rescale acc (packed), then PV accumulate (packed)
        u64 fv[4];
#pragma unroll
        for (int v = 0; v < 4; v++) fv[v] = *(const u64*)&S->fac[mB + 32 * v];
#pragma unroll
        for (int u = 0; u < 8; u++)
#pragma unroll
            for (int v = 0; v < 4; v++) acc[u][v] = fmul2(acc[u][v], fv[v]);

#pragma unroll
        for (int k = 0; k < 32; k++) {
            u64 ar[8], br[4];
#pragma unroll
            for (int u = 0; u < 8; u++) ar[u] = dup2(S->a[k][ty16 + 16 * u]);
#pragma unroll
            for (int v = 0; v < 4; v++) br[v] = *(const u64*)&S->p[k][mB + 32 * v];
#pragma unroll
            for (int u = 0; u < 8; u++)
#pragma unroll
                for (int v = 0; v < 4; v++) acc[u][v] = ffma2(br[v], ar[u], acc[u][v]);
        }
        __syncthreads();   // S0: done with this tile
    }

    // ---- epilogue: o = acc / l (packed stores)
    float* ob = g_o + (size_t)b * 128 * HW + m0;
    float rll[4], rlh[4];
#pragma unroll
    for (int v = 0; v < 4; v++) {
        rll[v] = 1.f / S->l[mB + 32 * v];
        rlh[v] = 1.f / S->l[mB + 32 * v + 1];
    }
#pragma unroll
    for (int u = 0; u < 8; u++) {
        int c = ty16 + 16 * u;
#pragma unroll
        for (int v = 0; v < 4; v++) {
            float lo, hi; upk2(lo, hi, acc[u][v]);
            *(float2*)&ob[(size_t)c * HW + mB + 32 * v] =
                make_float2(lo * rll[v], hi * rlh[v]);
        }
    }
}

// ---------------------------------------------------------------------------
// Kernel 3: out = gamma * BN(conv4(o)) + x. Packed f32x2 along oc pairs.
// grid (32 ptiles, 4 octiles, 8 b), 256 threads. Tile 64oc x 128p, K=128.
// Micro: 4 oc-PAIRS (oc = 2*ty + 16u) x 4 p (p = tx + 32v).
// ---------------------------------------------------------------------------
__global__ __launch_bounds__(256) void conv4_res_kernel(
    const float* __restrict__ x,
    const float* __restrict__ w4, const float* __restrict__ b4, const float* __restrict__ s4,
    const float* __restrict__ t4, const float* __restrict__ m4, const float* __restrict__ v4,
    const float* __restrict__ gamma, float* __restrict__ out)
{
    __shared__ float w_s[32][64];    // [k][oc]  rows 256B -> 8B aligned
    __shared__ float o_s[32][128];   // [k][p]
    int b = blockIdx.z, oc0 = blockIdx.y * 64, p0 = blockIdx.x * 128;
    int tid = threadIdx.x, ty = tid >> 5, tx = tid & 31;

    const float* ob = g_o + (size_t)b * 128 * HW + p0;

    u64 acc[4][4];
#pragma unroll
    for (int u = 0; u < 4; u++)
#pragma unroll
        for (int v = 0; v < 4; v++) acc[u][v] = 0ull;

    for (int kc = 0; kc < 128; kc += 32) {
#pragma unroll
        for (int e = tid; e < 2048; e += 256) { int k = e >> 6, oc = e & 63; w_s[k][oc] = w4[(size_t)(oc0 + oc) * 128 + kc + k]; }
#pragma unroll
        for (int e = tid; e < 4096; e += 256) { int k = e >> 7, p = e & 127; o_s[k][p] = ob[(size_t)(kc + k) * HW + p]; }
        __syncthreads();
#pragma unroll
        for (int k = 0; k < 32; k++) {
            u64 wr[4], pr[4];
#pragma unroll
            for (int u = 0; u < 4; u++) wr[u] = *(const u64*)&w_s[k][2 * ty + 16 * u];
#pragma unroll
            for (int v = 0; v < 4; v++) pr[v] = dup2(o_s[k][tx + 32 * v]);
#pragma unroll
            for (int u = 0; u < 4; u++)
#pragma unroll
                for (int v = 0; v < 4; v++) acc[u][v] = ffma2(wr[u], pr[v], acc[u][v]);
        }
        __syncthreads();
    }

    float gm = *gamma;
#pragma unroll
    for (int u = 0; u < 4; u++) {
        int ocA = oc0 + 2 * ty + 16 * u;
        int ocB = ocA + 1;
        float scA = s4[ocA] * rsqrtf(v4[ocA] + EPSV);
        float shA = (b4[ocA] - m4[ocA]) * scA + t4[ocA];
        float scB = s4[ocB] * rsqrtf(v4[ocB] + EPSV);
        float shB = (b4[ocB] - m4[ocB]) * scB + t4[ocB];
        const float* xpA = x   + ((size_t)b * CC + ocA) * HW + p0;
        float*       opA = out + ((size_t)b * CC + ocA) * HW + p0;
        const float* xpB = xpA + HW;
        float*       opB = opA + HW;
#pragma unroll
        for (int v = 0; v < 4; v++) {
            int p = tx + 32 * v;
            float lo, hi; upk2(lo, hi, acc[u][v]);
            opA[p] = gm * (lo * scA + shA) + xpA[p];
            opB[p] = gm * (hi * scB + shB) + xpB[p];
        }
    }
}

// ---------------------------------------------------------------------------
extern "C" void kernel_launch(void* const* d_in, const int* in_sizes, int n_in,
                              void* d_out, int out_size)
{
    (void)in_sizes; (void)n_in; (void)out_size;
    const float* x = (const float*)d_in[0];
#define P(i) ((const float*)d_in[i])

    conv123_kernel<<<dim3(16, 6, 8), 256>>>(
        x,
        P(1), P(2), P(3), P(4), P(5), P(6),        // conv1
        P(7), P(8), P(9), P(10), P(11), P(12),     // conv2
        P(13), P(14), P(15), P(16), P(17), P(18)); // conv3

    cudaFuncSetAttribute(flash_kernel, cudaFuncAttributeMaxDynamicSharedMemorySize,
                         (int)sizeof(FlashSmem));
    flash_kernel<<<dim3(32, 8), 256, sizeof(FlashSmem)>>>();

    conv4_res_kernel<<<dim3(32, 4, 8), 256>>>(
        x, P(19), P(20), P(21), P(22), P(23), P(24), P(25), (float*)d_out);
#undef P
}

// round 4
// speedup vs baseline: 2.0296x; 1.5148x over previous
#include <cuda_runtime.h>
#include <math.h>
#include <stdint.h>

// Problem constants
#define BB   8
#define CC   256
#define HW   4096
#define HW4  1024
#define EPSV 1e-5f

typedef unsigned long long u64;

// ---- packed f32x2 helpers (sm_103a) ----
__device__ __forceinline__ u64 dup2(float x) {
    u64 r; asm("mov.b64 %0, {%1, %1};" : "=l"(r) : "f"(x)); return r;
}
__device__ __forceinline__ void upk2(float& lo, float& hi, u64 v) {
    asm("mov.b64 {%0, %1}, %2;" : "=f"(lo), "=f"(hi) : "l"(v));
}
__device__ __forceinline__ u64 ffma2(u64 a, u64 b, u64 c) {
    u64 d; asm("fma.rn.f32x2 %0, %1, %2, %3;" : "=l"(d) : "l"(a), "l"(b), "l"(c)); return d;
}

// ---- tf32 helpers ----
__device__ __forceinline__ uint32_t tf32f(float x) {
    uint32_t r; asm("cvt.rna.tf32.f32 %0, %1;" : "=r"(r) : "f"(x)); return r;
}
// D(16x8,f32) += A(16x8,tf32) * B(8x8,tf32)
__device__ __forceinline__ void mma_tf32(float* c, const uint32_t* a, uint32_t b0, uint32_t b1) {
    asm volatile(
        "mma.sync.aligned.m16n8k8.row.col.f32.tf32.tf32.f32 "
        "{%0,%1,%2,%3}, {%4,%5,%6,%7}, {%8,%9}, {%0,%1,%2,%3};"
        : "+f"(c[0]), "+f"(c[1]), "+f"(c[2]), "+f"(c[3])
        : "r"(a[0]), "r"(a[1]), "r"(a[2]), "r"(a[3]), "r"(b0), "r"(b1));
}

// ---------------- scratch (static __device__ — allocation-free) ----------------
__device__ float g_g  [BB * 32 * HW];        //  4 MB  conv2 (g)  [b][k][m]
__device__ float g_f  [BB * 32 * HW4];       //  1 MB  pooled f   [b][k][n]
__device__ float g_hh [BB * 128 * HW4];      //  4 MB  pooled hh  [b][c][n]
__device__ float g_oT [(size_t)BB * HW * 128]; // 16 MB  oT       [b][m][c]

// ---------------------------------------------------------------------------
// Kernel 1: fused conv1/conv2/conv3 (1x1 conv + BN + ReLU), 2x2 maxpool in
// registers for conv1/conv3. (unchanged from round 3)
// ---------------------------------------------------------------------------
__global__ __launch_bounds__(256) void conv123_kernel(
    const float* __restrict__ x,
    const float* __restrict__ w1, const float* __restrict__ b1, const float* __restrict__ s1,
    const float* __restrict__ t1, const float* __restrict__ m1, const float* __restrict__ v1,
    const float* __restrict__ w2, const float* __restrict__ b2, const float* __restrict__ s2,
    const float* __restrict__ t2, const float* __restrict__ m2, const float* __restrict__ v2,
    const float* __restrict__ w3, const float* __restrict__ b3, const float* __restrict__ s3,
    const float* __restrict__ t3, const float* __restrict__ m3, const float* __restrict__ v3)
{
    __shared__ float w_s[32][32];
    __shared__ float x_s[32][256];

    int sel = blockIdx.y;
    const float *w, *pb, *ps, *pt, *pm, *pv;
    int oc0;
    if (sel == 0)      { w = w1; pb = b1; ps = s1; pt = t1; pm = m1; pv = v1; oc0 = 0; }
    else if (sel == 1) { w = w2; pb = b2; ps = s2; pt = t2; pm = m2; pv = v2; oc0 = 0; }
    else               { w = w3; pb = b3; ps = s3; pt = t3; pm = m3; pv = v3; oc0 = (sel - 2) * 32; }

    int b  = blockIdx.z;
    int p0 = blockIdx.x * 256;
    int tid = threadIdx.x, ty = tid >> 5, tx = tid & 31;

    const float* xb = x + (size_t)b * CC * HW + p0;

    u64 acc[4][4];
#pragma unroll
    for (int u = 0; u < 4; u++)
#pragma unroll
        for (int v = 0; v < 4; v++) acc[u][v] = 0ull;

    for (int kc = 0; kc < CC; kc += 32) {
#pragma unroll
        for (int e = tid; e < 32 * 32; e += 256) {
            int k = e >> 5, oc = e & 31;
            w_s[k][oc] = w[(size_t)(oc0 + oc) * CC + kc + k];
        }
#pragma unroll
        for (int e = tid; e < 32 * 64; e += 256) {
            int k = e >> 6, p4 = e & 63;
            float4 val = *(const float4*)(xb + (size_t)(kc + k) * HW + p4 * 4);
            *(float4*)&x_s[k][p4 * 4] = val;
        }
        __syncthreads();
#pragma unroll
        for (int k = 0; k < 32; k++) {
            u64 wr[4], xr[4];
#pragma unroll
            for (int u = 0; u < 4; u++) wr[u] = dup2(w_s[k][ty * 4 + u]);
#pragma unroll
            for (int v = 0; v < 4; v++) xr[v] = *(const u64*)&x_s[k][2 * tx + 64 * v];
#pragma unroll
            for (int u = 0; u < 4; u++)
#pragma unroll
                for (int v = 0; v < 4; v++) acc[u][v] = ffma2(xr[v], wr[u], acc[u][v]);
        }
        __syncthreads();
    }

    if (sel == 1) {
#pragma unroll
        for (int u = 0; u < 4; u++) {
            int oc = ty * 4 + u;
            float sc = ps[oc] * rsqrtf(pv[oc] + EPSV);
            float sh = (pb[oc] - pm[oc]) * sc + pt[oc];
            float* op = g_g + ((size_t)b * 32 + oc) * HW + p0;
#pragma unroll
            for (int v = 0; v < 4; v++) {
                float lo, hi; upk2(lo, hi, acc[u][v]);
                *(float2*)&op[2 * tx + 64 * v] =
                    make_float2(fmaxf(lo * sc + sh, 0.f), fmaxf(hi * sc + sh, 0.f));
            }
        }
        return;
    }

    int PR0 = p0 >> 7;
    float* out = (sel == 0) ? (g_f + (size_t)b * 32 * HW4)
                            : (g_hh + (size_t)b * 128 * HW4 + (size_t)oc0 * HW4);
#pragma unroll
    for (int u = 0; u < 4; u++) {
        int ocl = ty * 4 + u;
        int oc  = oc0 + ocl;
        float sc = ps[oc] * rsqrtf(pv[oc] + EPSV);
        float sh = (pb[oc] - pm[oc]) * sc + pt[oc];
        float hm[4];
#pragma unroll
        for (int v = 0; v < 4; v++) {
            float lo, hi; upk2(lo, hi, acc[u][v]);
            hm[v] = fmaxf(fmaxf(lo * sc + sh, 0.f), fmaxf(hi * sc + sh, 0.f));
        }
        out[(size_t)ocl * HW4 + (PR0 + 0) * 32 + tx] = fmaxf(hm[0], hm[1]);
        out[(size_t)ocl * HW4 + (PR0 + 1) * 32 + tx] = fmaxf(hm[2], hm[3]);
    }
}

// ---------------------------------------------------------------------------
// Kernel 2: flash attention on tensor cores (mma.sync m16n8k8 tf32).
//   sT[m][n] = sum_k g[k][m] f[k][n]; softmax over n (row-wise in sT);
//   oT[m][c] = sum_n p[m][n] hh[c][n].
// grid (32 mtiles, 8 b), 256 thr = 8 warps. m-tile 128 (16 rows/warp),
// n-tile 32. Softmax fully register-resident (quad shfl reductions).
// ---------------------------------------------------------------------------
__global__ __launch_bounds__(256) void flash_mma_kernel()
{
    // B-fragments pre-permuted: [tile][chunk][lane][4] -> conflict-free LDS.128
    __shared__ __align__(16) uint32_t fB[4][2][32][4];    //  4 KB (QK B: f)
    __shared__ __align__(16) uint32_t hB[16][2][32][4];   // 16 KB (PV B: hh)
    __shared__ __align__(16) uint32_t pS[8][16][36];      // 18 KB warp-private p

    int b = blockIdx.y, m0 = blockIdx.x * 128;
    int tid  = threadIdx.x;
    int lane = tid & 31, warp = tid >> 5;
    int q = lane & 3, r = lane >> 2;        // quad col / quad row

    const float* gb = g_g  + (size_t)b * 32  * HW  + m0 + warp * 16;
    const float* fb = g_f  + (size_t)b * 32  * HW4;
    const float* hb = g_hh + (size_t)b * 128 * HW4;

    // ---- g A-fragments: tile-invariant, load once. A[m][k] = g[k][m].
    uint32_t gA[4][4];
#pragma unroll
    for (int kc = 0; kc < 4; kc++) {
        gA[kc][0] = tf32f(gb[(size_t)(kc * 8 + q)     * HW + r]);
        gA[kc][1] = tf32f(gb[(size_t)(kc * 8 + q)     * HW + r + 8]);
        gA[kc][2] = tf32f(gb[(size_t)(kc * 8 + q + 4) * HW + r]);
        gA[kc][3] = tf32f(gb[(size_t)(kc * 8 + q + 4) * HW + r + 8]);
    }

    float mx0 = -INFINITY, mx1 = -INFINITY, l0 = 0.f, l1 = 0.f;
    float acc[16][4];
#pragma unroll
    for (int cc = 0; cc < 16; cc++)
#pragma unroll
        for (int i = 0; i < 4; i++) acc[cc][i] = 0.f;

    for (int n0 = 0; n0 < HW4; n0 += 32) {
        // ---- cooperative fragment fills (fragment-order, tf32-converted)
#pragma unroll
        for (int e = tid; e < 1024; e += 256) {
            int t_ = e & 3, ln = (e >> 2) & 31, ch = (e >> 7) & 1, nc = e >> 8;
            int k = (ln & 3) + 4 * (ch * 4 + t_);
            int n = nc * 8 + (ln >> 2);
            fB[nc][ch][ln][t_] = tf32f(fb[(size_t)k * HW4 + n0 + n]);
        }
#pragma unroll
        for (int e = tid; e < 4096; e += 256) {
            int t_ = e & 3, ln = (e >> 2) & 31, ch = (e >> 7) & 1, cc = e >> 8;
            int k = (ln & 3) + 4 * (ch * 4 + t_);
            int c = cc * 8 + (ln >> 2);
            hB[cc][ch][ln][t_] = tf32f(hb[(size_t)c * HW4 + n0 + k]);
        }
        __syncthreads();

        // ---- QK: sT[16m x 32n] per warp
        float s[4][4];
#pragma unroll
        for (int nc = 0; nc < 4; nc++)
#pragma unroll
            for (int i = 0; i < 4; i++) s[nc][i] = 0.f;
#pragma unroll
        for (int nc = 0; nc < 4; nc++) {
            uint4 f0 = *(const uint4*)fB[nc][0][lane];
            uint4 f1 = *(const uint4*)fB[nc][1][lane];
            mma_tf32(s[nc], gA[0], f0.x, f0.y);
            mma_tf32(s[nc], gA[1], f0.z, f0.w);
            mma_tf32(s[nc], gA[2], f1.x, f1.y);
            mma_tf32(s[nc], gA[3], f1.z, f1.w);
        }

        // ---- row max (rows r, r+8), quad reduction
        float t0 = fmaxf(fmaxf(s[0][0], s[0][1]), fmaxf(s[1][0], s[1][1]));
        t0 = fmaxf(t0, fmaxf(fmaxf(s[2][0], s[2][1]), fmaxf(s[3][0], s[3][1])));
        float t1 = fmaxf(fmaxf(s[0][2], s[0][3]), fmaxf(s[1][2], s[1][3]));
        t1 = fmaxf(t1, fmaxf(fmaxf(s[2][2], s[2][3]), fmaxf(s[3][2], s[3][3])));
        t0 = fmaxf(t0, __shfl_xor_sync(0xffffffffu, t0, 1));
        t0 = fmaxf(t0, __shfl_xor_sync(0xffffffffu, t0, 2));
        t1 = fmaxf(t1, __shfl_xor_sync(0xffffffffu, t1, 1));
        t1 = fmaxf(t1, __shfl_xor_sync(0xffffffffu, t1, 2));
        float nm0 = fmaxf(mx0, t0), nm1 = fmaxf(mx1, t1);
        float fac0 = __expf(mx0 - nm0), fac1 = __expf(mx1 - nm1);
        mx0 = nm0; mx1 = nm1;

        // ---- p = exp(s - mx), partial row sums, store p (tf32) to warp smem
        float ps0 = 0.f, ps1 = 0.f;
#pragma unroll
        for (int nc = 0; nc < 4; nc++) {
            float e0 = __expf(s[nc][0] - mx0);
            float e1 = __expf(s[nc][1] - mx0);
            float e2 = __expf(s[nc][2] - mx1);
            float e3 = __expf(s[nc][3] - mx1);
            ps0 += e0 + e1; ps1 += e2 + e3;
            *(uint2*)&pS[warp][r]    [nc * 8 + 2 * q] = make_uint2(tf32f(e0), tf32f(e1));
            *(uint2*)&pS[warp][r + 8][nc * 8 + 2 * q] = make_uint2(tf32f(e2), tf32f(e3));
        }
        ps0 += __shfl_xor_sync(0xffffffffu, ps0, 1);
        ps0 += __shfl_xor_sync(0xffffffffu, ps0, 2);
        ps1 += __shfl_xor_sync(0xffffffffu, ps1, 1);
        ps1 += __shfl_xor_sync(0xffffffffu, ps1, 2);
        l0 = l0 * fac0 + ps0;
        l1 = l1 * fac1 + ps1;

        // ---- rescale accumulator rows
#pragma unroll
        for (int cc = 0; cc < 16; cc++) {
            acc[cc][0] *= fac0; acc[cc][1] *= fac0;
            acc[cc][2] *= fac1; acc[cc][3] *= fac1;
        }

        __syncwarp();
        // ---- p A-fragments (conflict-free: bank = lane)
        uint32_t pA[4][4];
#pragma unroll
        for (int kc = 0; kc < 4; kc++) {
            pA[kc][0] = pS[warp][r]    [kc * 8 + q];
            pA[kc][1] = pS[warp][r + 8][kc * 8 + q];
            pA[kc][2] = pS[warp][r]    [kc * 8 + q + 4];
            pA[kc][3] = pS[warp][r + 8][kc * 8 + q + 4];
        }

        // ---- PV: oT[16m x 128c] += p[16m x 32n] * hhT[32n x 128c]
#pragma unroll
        for (int cc = 0; cc < 16; cc++) {
            uint4 h0 = *(const uint4*)hB[cc][0][lane];
            uint4 h1 = *(const uint4*)hB[cc][1][lane];
            mma_tf32(acc[cc], pA[0], h0.x, h0.y);
            mma_tf32(acc[cc], pA[1], h0.z, h0.w);
            mma_tf32(acc[cc], pA[2], h1.x, h1.y);
            mma_tf32(acc[cc], pA[3], h1.z, h1.w);
        }
        __syncthreads();
    }

    // ---- epilogue: oT[m][c] = acc / l, coalesced float2 stores
    float rl0 = 1.f / l0, rl1 = 1.f / l1;
    float* ot = g_oT + ((size_t)b * HW + m0 + warp * 16) * 128;
#pragma unroll
    for (int cc = 0; cc < 16; cc++) {
        int c = cc * 8 + 2 * q;
        *(float2*)&ot[(size_t)r * 128 + c] =
            make_float2(acc[cc][0] * rl0, acc[cc][1] * rl0);
        *(float2*)&ot[(size_t)(r + 8) * 128 + c] =
            make_float2(acc[cc][2] * rl1, acc[cc][3] * rl1);
    }
}

// ---------------------------------------------------------------------------
// Kernel 3: out = gamma * BN(conv4(o)) + x, o read from transposed oT[m][c].
// grid (32 ptiles, 4 octiles, 8 b), 256 threads. Tile 64oc x 128p, K=128.
// ---------------------------------------------------------------------------
__global__ __launch_bounds__(256) void conv4_res_kernel(
    const float* __restrict__ x,
    const float* __restrict__ w4, const float* __restrict__ b4, const float* __restrict__ s4,
    const float* __restrict__ t4, const float* __restrict__ m4, const float* __restrict__ v4,
    const float* __restrict__ gamma, float* __restrict__ out)
{
    __shared__ float w_s[32][64];
    __shared__ float o_s[32][133];   // pad 133: conflict-free transpose stores
    int b = blockIdx.z, oc0 = blockIdx.y * 64, p0 = blockIdx.x * 128;
    int tid = threadIdx.x, ty = tid >> 5, tx = tid & 31;

    const float* obT = g_oT + (size_t)b * HW * 128 + (size_t)p0 * 128;

    u64 acc[4][4];
#pragma unroll
    for (int u = 0; u < 4; u++)
#pragma unroll
        for (int v = 0; v < 4; v++) acc[u][v] = 0ull;

    for (int kc = 0; kc < 128; kc += 32) {
#pragma unroll
        for (int e = tid; e < 2048; e += 256) {
            int k = e >> 6, oc = e & 63;
            w_s[k][oc] = w4[(size_t)(oc0 + oc) * 128 + kc + k];
        }
        // transposed coalesced load: float4 along c, scatter into o_s[k][p]
#pragma unroll
        for (int e = tid; e < 1024; e += 256) {
            int p = e >> 3, kg = e & 7;
            float4 v = *(const float4*)&obT[(size_t)p * 128 + kc + kg * 4];
            o_s[kg * 4 + 0][p] = v.x;
            o_s[kg * 4 + 1][p] = v.y;
            o_s[kg * 4 + 2][p] = v.z;
            o_s[kg * 4 + 3][p] = v.w;
        }
        __syncthreads();
#pragma unroll
        for (int k = 0; k < 32; k++) {
            u64 wr[4], pr[4];
#pragma unroll
            for (int u = 0; u < 4; u++) wr[u] = *(const u64*)&w_s[k][2 * ty + 16 * u];
#pragma unroll
            for (int v = 0; v < 4; v++) pr[v] = dup2(o_s[k][tx + 32 * v]);
#pragma unroll
            for (int u = 0; u < 4; u++)
#pragma unroll
                for (int v = 0; v < 4; v++) acc[u][v] = ffma2(wr[u], pr[v], acc[u][v]);
        }
        __syncthreads();
    }

    float gm = *gamma;
#pragma unroll
    for (int u = 0; u < 4; u++) {
        int ocA = oc0 + 2 * ty + 16 * u;
        int ocB = ocA + 1;
        float scA = s4[ocA] * rsqrtf(v4[ocA] + EPSV);
        float shA = (b4[ocA] - m4[ocA]) * scA + t4[ocA];
        float scB = s4[ocB] * rsqrtf(v4[ocB] + EPSV);
        float shB = (b4[ocB] - m4[ocB]) * scB + t4[ocB];
        const float* xpA = x   + ((size_t)b * CC + ocA) * HW + p0;
        float*       opA = out + ((size_t)b * CC + ocA) * HW + p0;
        const float* xpB = xpA + HW;
        float*       opB = opA + HW;
#pragma unroll
        for (int v = 0; v < 4; v++) {
            int p = tx + 32 * v;
            float lo, hi; upk2(lo, hi, acc[u][v]);
            opA[p] = gm * (lo * scA + shA) + xpA[p];
            opB[p] = gm * (hi * scB + shB) + xpB[p];
        }
    }
}

// ---------------------------------------------------------------------------
extern "C" void kernel_launch(void* const* d_in, const int* in_sizes, int n_in,
                              void* d_out, int out_size)
{
    (void)in_sizes; (void)n_in; (void)out_size;
    const float* x = (const float*)d_in[0];
#define P(i) ((const float*)d_in[i])

    conv123_kernel<<<dim3(16, 6, 8), 256>>>(
        x,
        P(1), P(2), P(3), P(4), P(5), P(6),        // conv1
        P(7), P(8), P(9), P(10), P(11), P(12),     // conv2
        P(13), P(14), P(15), P(16), P(17), P(18)); // conv3

    flash_mma_kernel<<<dim3(32, 8), 256>>>();

    conv4_res_kernel<<<dim3(32, 4, 8), 256>>>(
        x, P(19), P(20), P(21), P(22), P(23), P(24), P(25), (float*)d_out);
#undef P
}

// round 6
// speedup vs baseline: 2.3328x; 1.1494x over previous
#include <cuda_runtime.h>
#include <math.h>
#include <stdint.h>

// Problem constants
#define BB   8
#define CC   256
#define HW   4096
#define HW4  1024
#define EPSV 1e-5f

// ---- tf32 helpers ----
__device__ __forceinline__ uint32_t tf32f(float x) {
    uint32_t r; asm("cvt.rna.tf32.f32 %0, %1;" : "=r"(r) : "f"(x)); return r;
}
// D(16x8,f32) += A(16x8,tf32) * B(8x8,tf32)
__device__ __forceinline__ void mma_tf32(float* c, const uint32_t* a, uint32_t b0, uint32_t b1) {
    asm volatile(
        "mma.sync.aligned.m16n8k8.row.col.f32.tf32.tf32.f32 "
        "{%0,%1,%2,%3}, {%4,%5,%6,%7}, {%8,%9}, {%0,%1,%2,%3};"
        : "+f"(c[0]), "+f"(c[1]), "+f"(c[2]), "+f"(c[3])
        : "r"(a[0]), "r"(a[1]), "r"(a[2]), "r"(a[3]), "r"(b0), "r"(b1));
}

// ---------------- scratch (static __device__ — allocation-free) ----------------
__device__ float g_g  [BB * 32 * HW];          //  4 MB  conv2 (g)  [b][k][m]
__device__ float g_f  [BB * 32 * HW4];         //  1 MB  pooled f   [b][k][n]
__device__ float g_hh [BB * 128 * HW4];        //  4 MB  pooled hh  [b][c][n]
__device__ float g_oT [(size_t)BB * HW * 128]; // 16 MB  oT         [b][m][c]

// ---------------------------------------------------------------------------
// Kernel 1: fused conv1/conv2/conv3 (1x1 conv + BN + ReLU) on tensor cores.
// grid (16 pixtiles, 6 sel, 8 b), 256 thr = 8 warps.
// CTA tile: 32 oc x 256 pix, K=256 in chunks of 32 (tf32-staged smem).
// Warp: 2 m16-frags (32 oc) x 4 n8-frags (32 pix).
// Epilogue: BN+ReLU staged to smem; pooled (sel 0,2..5) or full (sel 1) write.
// ---------------------------------------------------------------------------
__global__ __launch_bounds__(256) void conv123_mma_kernel(
    const float* __restrict__ x,
    const float* __restrict__ w1, const float* __restrict__ b1, const float* __restrict__ s1,
    const float* __restrict__ t1, const float* __restrict__ m1, const float* __restrict__ v1,
    const float* __restrict__ w2, const float* __restrict__ b2, const float* __restrict__ s2,
    const float* __restrict__ t2, const float* __restrict__ m2, const float* __restrict__ v2,
    const float* __restrict__ w3, const float* __restrict__ b3, const float* __restrict__ s3,
    const float* __restrict__ t3, const float* __restrict__ m3, const float* __restrict__ v3)
{
    __shared__ __align__(16) uint32_t w_s[32 * 33];    // [oc][k] tf32, padded
    __shared__ __align__(16) uint32_t x_s[32 * 258];   // [k][pix] tf32; reused as y_s

    int sel = blockIdx.y;
    const float *w, *pb, *ps, *pt, *pm, *pv;
    int oc0;
    if (sel == 0)      { w = w1; pb = b1; ps = s1; pt = t1; pm = m1; pv = v1; oc0 = 0; }
    else if (sel == 1) { w = w2; pb = b2; ps = s2; pt = t2; pm = m2; pv = v2; oc0 = 0; }
    else               { w = w3; pb = b3; ps = s3; pt = t3; pm = m3; pv = v3; oc0 = (sel - 2) * 32; }

    int b  = blockIdx.z;
    int p0 = blockIdx.x * 256;
    int tid = threadIdx.x, lane = tid & 31, warp = tid >> 5;
    int q = lane & 3, r = lane >> 2;

    const float* xb = x + (size_t)b * CC * HW + p0;

    float acc[2][4][4];
#pragma unroll
    for (int mt = 0; mt < 2; mt++)
#pragma unroll
        for (int nc = 0; nc < 4; nc++)
#pragma unroll
            for (int i = 0; i < 4; i++) acc[mt][nc][i] = 0.f;

    for (int kc0 = 0; kc0 < CC; kc0 += 32) {
        // stage w chunk [32oc][32k] (tf32)
        {
            int oc = tid >> 3, kg = tid & 7;
            float4 wv = *(const float4*)&w[(size_t)(oc0 + oc) * CC + kc0 + kg * 4];
            uint32_t* d = &w_s[oc * 33 + kg * 4];
            d[0] = tf32f(wv.x); d[1] = tf32f(wv.y); d[2] = tf32f(wv.z); d[3] = tf32f(wv.w);
        }
        // stage x chunk [32k][256pix] (tf32)
#pragma unroll
        for (int j = 0; j < 8; j++) {
            int e = tid + 256 * j;
            int k = e >> 6, p4 = e & 63;
            float4 xv = *(const float4*)&xb[(size_t)(kc0 + k) * HW + p4 * 4];
            uint32_t* d = &x_s[k * 258 + p4 * 4];
            d[0] = tf32f(xv.x); d[1] = tf32f(xv.y); d[2] = tf32f(xv.z); d[3] = tf32f(xv.w);
        }
        __syncthreads();

        int nbase = warp * 32 + r;
#pragma unroll
        for (int kc = 0; kc < 4; kc++) {
            uint32_t a[2][4];
#pragma unroll
            for (int mt = 0; mt < 2; mt++) {
                a[mt][0] = w_s[(mt * 16 + r) * 33 + kc * 8 + q];
                a[mt][1] = w_s[(mt * 16 + r + 8) * 33 + kc * 8 + q];
                a[mt][2] = w_s[(mt * 16 + r) * 33 + kc * 8 + q + 4];
                a[mt][3] = w_s[(mt * 16 + r + 8) * 33 + kc * 8 + q + 4];
            }
#pragma unroll
            for (int nc = 0; nc < 4; nc++) {
                uint32_t bb0 = x_s[(kc * 8 + q) * 258 + nbase + nc * 8];
                uint32_t bb1 = x_s[(kc * 8 + q + 4) * 258 + nbase + nc * 8];
                mma_tf32(acc[0][nc], a[0], bb0, bb1);
                mma_tf32(acc[1][nc], a[1], bb0, bb1);
            }
        }
        __syncthreads();
    }

    // ---- epilogue: BN(+ReLU) into smem staging (reuse x_s), then write out
    float* y_s = (float*)x_s;
    float gsc[2][2], gsh[2][2];
#pragma unroll
    for (int mt = 0; mt < 2; mt++)
#pragma unroll
        for (int h2 = 0; h2 < 2; h2++) {
            int oc = oc0 + mt * 16 + r + 8 * h2;
            float sc = ps[oc] * rsqrtf(pv[oc] + EPSV);
            gsc[mt][h2] = sc;
            gsh[mt][h2] = (pb[oc] - pm[oc]) * sc + pt[oc];
        }
#pragma unroll
    for (int mt = 0; mt < 2; mt++)
#pragma unroll
        for (int nc = 0; nc < 4; nc++) {
            int col = warp * 32 + nc * 8 + 2 * q;
            float2 v0 = make_float2(
                fmaxf(acc[mt][nc][0] * gsc[mt][0] + gsh[mt][0], 0.f),
                fmaxf(acc[mt][nc][1] * gsc[mt][0] + gsh[mt][0], 0.f));
            float2 v1 = make_float2(
                fmaxf(acc[mt][nc][2] * gsc[mt][1] + gsh[mt][1], 0.f),
                fmaxf(acc[mt][nc][3] * gsc[mt][1] + gsh[mt][1], 0.f));
            *(float2*)&y_s[(mt * 16 + r) * 258 + col]     = v0;
            *(float2*)&y_s[(mt * 16 + r + 8) * 258 + col] = v1;
        }
    __syncthreads();

    if (sel == 1) {
        float* op = g_g + (size_t)b * 32 * HW + p0;
#pragma unroll
        for (int j = 0; j < 32; j++) {
            int e = tid + 256 * j;
            int oc = e >> 8, pix = e & 255;
            op[(size_t)oc * HW + pix] = y_s[oc * 258 + pix];
        }
        return;
    }

    // pooled write (conv1 -> g_f, conv3 -> g_hh)
    int PR0 = p0 >> 7;
    float* outp = (sel == 0) ? (g_f + (size_t)b * 32 * HW4)
                             : (g_hh + (size_t)b * 128 * HW4 + (size_t)oc0 * HW4);
#pragma unroll
    for (int j = 0; j < 8; j++) {
        int e = tid + 256 * j;        // < 2048
        int ocl = e >> 6, qq = e & 63;
        int pq = qq >> 5, col = qq & 31;
        int base = ocl * 258 + pq * 128 + 2 * col;
        float v01 = fmaxf(y_s[base],      y_s[base + 1]);
        float v23 = fmaxf(y_s[base + 64], y_s[base + 65]);
        outp[(size_t)ocl * HW4 + (PR0 + pq) * 32 + col] = fmaxf(v01, v23);
    }
}

// ---------------------------------------------------------------------------
// Kernel 2: flash attention on tensor cores (unchanged from round 4).
// ---------------------------------------------------------------------------
__global__ __launch_bounds__(256) void flash_mma_kernel()
{
    __shared__ __align__(16) uint32_t fB[4][2][32][4];    //  4 KB (QK B: f)
    __shared__ __align__(16) uint32_t hB[16][2][32][4];   // 16 KB (PV B: hh)
    __shared__ __align__(16) uint32_t pS[8][16][36];      // 18 KB warp-private p

    int b = blockIdx.y, m0 = blockIdx.x * 128;
    int tid  = threadIdx.x;
    int lane = tid & 31, warp = tid >> 5;
    int q = lane & 3, r = lane >> 2;

    const float* gb = g_g  + (size_t)b * 32  * HW  + m0 + warp * 16;
    const float* fb = g_f  + (size_t)b * 32  * HW4;
    const float* hb = g_hh + (size_t)b * 128 * HW4;

    uint32_t gA[4][4];
#pragma unroll
    for (int kc = 0; kc < 4; kc++) {
        gA[kc][0] = tf32f(gb[(size_t)(kc * 8 + q)     * HW + r]);
        gA[kc][1] = tf32f(gb[(size_t)(kc * 8 + q)     * HW + r + 8]);
        gA[kc][2] = tf32f(gb[(size_t)(kc * 8 + q + 4) * HW + r]);
        gA[kc][3] = tf32f(gb[(size_t)(kc * 8 + q + 4) * HW + r + 8]);
    }

    float mx0 = -INFINITY, mx1 = -INFINITY, l0 = 0.f, l1 = 0.f;
    float acc[16][4];
#pragma unroll
    for (int cc = 0; cc < 16; cc++)
#pragma unroll
        for (int i = 0; i < 4; i++) acc[cc][i] = 0.f;

    for (int n0 = 0; n0 < HW4; n0 += 32) {
#pragma unroll
        for (int e = tid; e < 1024; e += 256) {
            int t_ = e & 3, ln = (e >> 2) & 31, ch = (e >> 7) & 1, nc = e >> 8;
            int k = (ln & 3) + 4 * (ch * 4 + t_);
            int n = nc * 8 + (ln >> 2);
            fB[nc][ch][ln][t_] = tf32f(fb[(size_t)k * HW4 + n0 + n]);
        }
#pragma unroll
        for (int e = tid; e < 4096; e += 256) {
            int t_ = e & 3, ln = (e >> 2) & 31, ch = (e >> 7) & 1, cc = e >> 8;
            int k = (ln & 3) + 4 * (ch * 4 + t_);
            int c = cc * 8 + (ln >> 2);
            hB[cc][ch][ln][t_] = tf32f(hb[(size_t)c * HW4 + n0 + k]);
        }
        __syncthreads();

        float s[4][4];
#pragma unroll
        for (int nc = 0; nc < 4; nc++)
#pragma unroll
            for (int i = 0; i < 4; i++) s[nc][i] = 0.f;
#pragma unroll
        for (int nc = 0; nc < 4; nc++) {
            uint4 f0 = *(const uint4*)fB[nc][0][lane];
            uint4 f1 = *(const uint4*)fB[nc][1][lane];
            mma_tf32(s[nc], gA[0], f0.x, f0.y);
            mma_tf32(s[nc], gA[1], f0.z, f0.w);
            mma_tf32(s[nc], gA[2], f1.x, f1.y);
            mma_tf32(s[nc], gA[3], f1.z, f1.w);
        }

        float t0 = fmaxf(fmaxf(s[0][0], s[0][1]), fmaxf(s[1][0], s[1][1]));
        t0 = fmaxf(t0, fmaxf(fmaxf(s[2][0], s[2][1]), fmaxf(s[3][0], s[3][1])));
        float t1 = fmaxf(fmaxf(s[0][2], s[0][3]), fmaxf(s[1][2], s[1][3]));
        t1 = fmaxf(t1, fmaxf(fmaxf(s[2][2], s[2][3]), fmaxf(s[3][2], s[3][3])));
        t0 = fmaxf(t0, __shfl_xor_sync(0xffffffffu, t0, 1));
        t0 = fmaxf(t0, __shfl_xor_sync(0xffffffffu, t0, 2));
        t1 = fmaxf(t1, __shfl_xor_sync(0xffffffffu, t1, 1));
        t1 = fmaxf(t1, __shfl_xor_sync(0xffffffffu, t1, 2));
        float nm0 = fmaxf(mx0, t0), nm1 = fmaxf(mx1, t1);
        float fac0 = __expf(mx0 - nm0), fac1 = __expf(mx1 - nm1);
        mx0 = nm0; mx1 = nm1;

        float ps0 = 0.f, ps1 = 0.f;
#pragma unroll
        for (int nc = 0; nc < 4; nc++) {
            float e0 = __expf(s[nc][0] - mx0);
            float e1 = __expf(s[nc][1] - mx0);
            float e2 = __expf(s[nc][2] - mx1);
            float e3 = __expf(s[nc][3] - mx1);
            ps0 += e0 + e1; ps1 += e2 + e3;
            *(uint2*)&pS[warp][r]    [nc * 8 + 2 * q] = make_uint2(tf32f(e0), tf32f(e1));
            *(uint2*)&pS[warp][r + 8][nc * 8 + 2 * q] = make_uint2(tf32f(e2), tf32f(e3));
        }
        ps0 += __shfl_xor_sync(0xffffffffu, ps0, 1);
        ps0 += __shfl_xor_sync(0xffffffffu, ps0, 2);
        ps1 += __shfl_xor_sync(0xffffffffu, ps1, 1);
        ps1 += __shfl_xor_sync(0xffffffffu, ps1, 2);
        l0 = l0 * fac0 + ps0;
        l1 = l1 * fac1 + ps1;

#pragma unroll
        for (int cc = 0; cc < 16; cc++) {
            acc[cc][0] *= fac0; acc[cc][1] *= fac0;
            acc[cc][2] *= fac1; acc[cc][3] *= fac1;
        }

        __syncwarp();
        uint32_t pA[4][4];
#pragma unroll
        for (int kc = 0; kc < 4; kc++) {
            pA[kc][0] = pS[warp][r]    [kc * 8 + q];
            pA[kc][1] = pS[warp][r + 8][kc * 8 + q];
            pA[kc][2] = pS[warp][r]    [kc * 8 + q + 4];
            pA[kc][3] = pS[warp][r + 8][kc * 8 + q + 4];
        }

#pragma unroll
        for (int cc = 0; cc < 16; cc++) {
            uint4 h0 = *(const uint4*)hB[cc][0][lane];
            uint4 h1 = *(const uint4*)hB[cc][1][lane];
            mma_tf32(acc[cc], pA[0], h0.x, h0.y);
            mma_tf32(acc[cc], pA[1], h0.z, h0.w);
            mma_tf32(acc[cc], pA[2], h1.x, h1.y);
            mma_tf32(acc[cc], pA[3], h1.z, h1.w);
        }
        __syncthreads();
    }

    float rl0 = 1.f / l0, rl1 = 1.f / l1;
    float* ot = g_oT + ((size_t)b * HW + m0 + warp * 16) * 128;
#pragma unroll
    for (int cc = 0; cc < 16; cc++) {
        int c = cc * 8 + 2 * q;
        *(float2*)&ot[(size_t)r * 128 + c] =
            make_float2(acc[cc][0] * rl0, acc[cc][1] * rl0);
        *(float2*)&ot[(size_t)(r + 8) * 128 + c] =
            make_float2(acc[cc][2] * rl1, acc[cc][3] * rl1);
    }
}

// ---------------------------------------------------------------------------
// Kernel 3: out = gamma * BN(conv4(o)) + x, on tensor cores.
// grid (64 pixtiles, 2 octiles, 8 b), 256 thr = 8 warps.
// CTA: 128 oc x 64 pix, K=128 (OC total = 256 via blockIdx.y).
// B operand is g_oT[m][c] directly (col-major k x n). Warp: 1 m16 x 8 n8.
// ---------------------------------------------------------------------------
__global__ __launch_bounds__(256) void conv4_mma_kernel(
    const float* __restrict__ x,
    const float* __restrict__ w4, const float* __restrict__ b4, const float* __restrict__ s4,
    const float* __restrict__ t4, const float* __restrict__ m4, const float* __restrict__ v4,
    const float* __restrict__ gamma, float* __restrict__ out)
{
    __shared__ __align__(16) uint32_t w4_s[128 * 33];   // [oc][k] tf32, padded
    __shared__ __align__(16) uint32_t o_s [64 * 33];    // [pix][k] tf32, padded

    int b = blockIdx.z, oc0 = blockIdx.y * 128, p0 = blockIdx.x * 64;
    int tid = threadIdx.x, lane = tid & 31, warp = tid >> 5;
    int q = lane & 3, r = lane >> 2;

    const float* obT = g_oT + (size_t)b * HW * 128 + (size_t)p0 * 128;

    float acc[8][4];
#pragma unroll
    for (int nc = 0; nc < 8; nc++)
#pragma unroll
        for (int i = 0; i < 4; i++) acc[nc][i] = 0.f;

    for (int kc0 = 0; kc0 < 128; kc0 += 32) {
        // stage w4 chunk [128oc][32k]
#pragma unroll
        for (int j = 0; j < 4; j++) {
            int e = tid + 256 * j;
            int oc = e >> 3, kg = e & 7;
            float4 wv = *(const float4*)&w4[(size_t)(oc0 + oc) * 128 + kc0 + kg * 4];
            uint32_t* d = &w4_s[oc * 33 + kg * 4];
            d[0] = tf32f(wv.x); d[1] = tf32f(wv.y); d[2] = tf32f(wv.z); d[3] = tf32f(wv.w);
        }
        // stage oT chunk [64pix][32k]
#pragma unroll
        for (int j = 0; j < 2; j++) {
            int e = tid + 256 * j;
            int n = e >> 3, kg = e & 7;
            float4 ov = *(const float4*)&obT[(size_t)n * 128 + kc0 + kg * 4];
            uint32_t* d = &o_s[n * 33 + kg * 4];
            d[0] = tf32f(ov.x); d[1] = tf32f(ov.y); d[2] = tf32f(ov.z); d[3] = tf32f(ov.w);
        }
        __syncthreads();

#pragma unroll
        for (int kc = 0; kc < 4; kc++) {
            uint32_t a[4];
            a[0] = w4_s[(warp * 16 + r) * 33 + kc * 8 + q];
            a[1] = w4_s[(warp * 16 + r + 8) * 33 + kc * 8 + q];
            a[2] = w4_s[(warp * 16 + r) * 33 + kc * 8 + q + 4];
            a[3] = w4_s[(warp * 16 + r + 8) * 33 + kc * 8 + q + 4];
#pragma unroll
            for (int nc = 0; nc < 8; nc++) {
                uint32_t bb0 = o_s[(nc * 8 + r) * 33 + kc * 8 + q];
                uint32_t bb1 = o_s[(nc * 8 + r) * 33 + kc * 8 + q + 4];
                mma_tf32(acc[nc], a, bb0, bb1);
            }
        }
        __syncthreads();
    }

    float gm = *gamma;
    int ocA = oc0 + warp * 16 + r, ocB = ocA + 8;
    float scA = s4[ocA] * rsqrtf(v4[ocA] + EPSV);
    float shA = (b4[ocA] - m4[ocA]) * scA + t4[ocA];
    float scB = s4[ocB] * rsqrtf(v4[ocB] + EPSV);
    float shB = (b4[ocB] - m4[ocB]) * scB + t4[ocB];
    const float* xpA = x   + ((size_t)b * CC + ocA) * HW + p0;
    float*       opA = out + ((size_t)b * CC + ocA) * HW + p0;
    const float* xpB = xpA + 8 * HW;
    float*       opB = opA + 8 * HW;
#pragma unroll
    for (int nc = 0; nc < 8; nc++) {
        int pix = nc * 8 + 2 * q;
        *(float2*)&opA[pix] = make_float2(
            gm * (acc[nc][0] * scA + shA) + xpA[pix],
            gm * (acc[nc][1] * scA + shA) + xpA[pix + 1]);
        *(float2*)&opB[pix] = make_float2(
            gm * (acc[nc][2] * scB + shB) + xpB[pix],
            gm * (acc[nc][3] * scB + shB) + xpB[pix + 1]);
    }
}

// ---------------------------------------------------------------------------
extern "C" void kernel_launch(void* const* d_in, const int* in_sizes, int n_in,
                              void* d_out, int out_size)
{
    (void)in_sizes; (void)n_in; (void)out_size;
    const float* x = (const float*)d_in[0];
#define P(i) ((const float*)d_in[i])

    conv123_mma_kernel<<<dim3(16, 6, 8), 256>>>(
        x,
        P(1), P(2), P(3), P(4), P(5), P(6),        // conv1
        P(7), P(8), P(9), P(10), P(11), P(12),     // conv2
        P(13), P(14), P(15), P(16), P(17), P(18)); // conv3

    flash_mma_kernel<<<dim3(32, 8), 256>>>();

    conv4_mma_kernel<<<dim3(64, 2, 8), 256>>>(
        x, P(19), P(20), P(21), P(22), P(23), P(24), P(25), (float*)d_out);
#undef P
}